// round 9
// baseline (speedup 1.0000x reference)
#include <cuda_runtime.h>

#define NN 100000
#define DD 64
#define NE 1200000

// scratch (all __device__ globals per allocation rules)
__device__ float    g_x1[NN * DD];      // 25.6 MB
__device__ float4   g_kept[2 * NE];     // 38.4 MB packed kept-edges, per layer
__device__ unsigned g_cnt[2];           // kept counts

// ---------------- packed f32x2 helpers (Blackwell FFMA2 path) ----------------
__device__ __forceinline__ unsigned long long pk2(float lo, float hi) {
    unsigned long long r;
    asm("mov.b64 %0, {%1, %2};" : "=l"(r) : "f"(lo), "f"(hi));
    return r;
}
__device__ __forceinline__ void upk2(float& lo, float& hi, unsigned long long v) {
    asm("mov.b64 {%0, %1}, %2;" : "=f"(lo), "=f"(hi) : "l"(v));
}
__device__ __forceinline__ void ffma2(unsigned long long& d,
                                      unsigned long long a,
                                      unsigned long long b) {
    asm("fma.rn.f32x2 %0, %1, %2, %0;" : "+l"(d) : "l"(a), "l"(b));
}

__device__ __forceinline__ void red_add_v4(float* addr, float a, float b,
                                           float c, float d) {
    asm volatile("red.global.add.v4.f32 [%0], {%1, %2, %3, %4};"
                 :: "l"(addr), "f"(a), "f"(b), "f"(c), "f"(d)
                 : "memory");
}

__global__ void zero_kernel(float* __restrict__ p, int n4) {
    int i = blockIdx.x * blockDim.x + threadIdx.x;
    if (i < n4) ((float4*)p)[i] = make_float4(0.f, 0.f, 0.f, 0.f);
    if (i < 2) g_cnt[i] = 0;
}

// Evaluate both layers' dropout, compact kept edges into packed float4
// {row, col, v, 0} with v pre-scaled (layer1 includes the final /3).
// Warp-aggregated atomic append -> warp-consecutive, coalesced stores.
__global__ void prep_kernel(const float* __restrict__ vals,
                            const float* __restrict__ du,
                            const int*   __restrict__ rows,
                            const int*   __restrict__ cols) {
    int e = blockIdx.x * blockDim.x + threadIdx.x;
    bool valid = e < NE;
    int idx = valid ? e : 0;

    float w  = vals[idx] / 0.7f;
    float u0 = du[idx];
    float u1 = du[idx + NE];
    int   r  = rows[idx];
    int   c  = cols[idx];

    bool k0 = valid && ((u0 + 0.7f) >= 1.0f);   // matches reference f32 exactly
    bool k1 = valid && ((u1 + 0.7f) >= 1.0f);
    int lane = threadIdx.x & 31;

    unsigned m0 = __ballot_sync(0xffffffffu, k0);
    if (m0) {
        int leader = __ffs(m0) - 1;
        unsigned base = 0;
        if (lane == leader) base = atomicAdd(&g_cnt[0], (unsigned)__popc(m0));
        base = __shfl_sync(0xffffffffu, base, leader);
        if (k0) {
            unsigned pos = base + __popc(m0 & ((1u << lane) - 1u));
            g_kept[pos] = make_float4(__int_as_float(r), __int_as_float(c), w, 0.f);
        }
    }
    unsigned m1 = __ballot_sync(0xffffffffu, k1);
    if (m1) {
        int leader = __ffs(m1) - 1;
        unsigned base = 0;
        if (lane == leader) base = atomicAdd(&g_cnt[1], (unsigned)__popc(m1));
        base = __shfl_sync(0xffffffffu, base, leader);
        if (k1) {
            unsigned pos = base + __popc(m1 & ((1u << lane) - 1u));
            g_kept[NE + pos] = make_float4(__int_as_float(r), __int_as_float(c),
                                           w * (1.0f / 3.0f), 0.f);
        }
    }
}

// Compact spmm: 8 lanes per kept edge, ILP2 (edges g and g+ceil(n/2)).
// Metadata = one broadcast LDG.128 per edge; no divergence in hot path.
__global__ void spmm_compact(const float* __restrict__ x,
                             const float4* __restrict__ kept,
                             const unsigned* __restrict__ cnt,
                             float* __restrict__ out) {
    unsigned gid  = blockIdx.x * blockDim.x + threadIdx.x;
    unsigned g    = gid >> 3;
    unsigned lane = gid & 7u;

    unsigned n = __ldg(cnt);
    unsigned h = (n + 1u) >> 1;
    if (g >= h) return;

    float4 md0 = kept[g];
    unsigned g1 = g + h;
    bool has1 = g1 < n;
    float4 md1 = has1 ? kept[g1] : md0;

    int   r0 = __float_as_int(md0.x), c0 = __float_as_int(md0.y);
    int   r1 = __float_as_int(md1.x), c1 = __float_as_int(md1.y);
    float v0 = md0.z, v1 = md1.z;

    const float4* s0 = (const float4*)(x + (size_t)c0 * DD);
    const float4* s1 = (const float4*)(x + (size_t)c1 * DD);
    float4 a0 = s0[lane];
    float4 a1 = s0[lane + 8];
    float4 b0, b1;
    if (has1) { b0 = s1[lane]; b1 = s1[lane + 8]; }

    float* d0 = out + (size_t)r0 * DD;
    red_add_v4(d0 + lane * 4,       v0 * a0.x, v0 * a0.y, v0 * a0.z, v0 * a0.w);
    red_add_v4(d0 + (lane + 8) * 4, v0 * a1.x, v0 * a1.y, v0 * a1.z, v0 * a1.w);
    if (has1) {
        float* d1 = out + (size_t)r1 * DD;
        red_add_v4(d1 + lane * 4,       v1 * b0.x, v1 * b0.y, v1 * b0.z, v1 * b0.w);
        red_add_v4(d1 + (lane + 8) * 4, v1 * b1.x, v1 * b1.y, v1 * b1.z, v1 * b1.w);
    }
}

// Register-tiled fc (unchanged from R6): out = (emb@W^T + b + x1)/3.
__global__ void __launch_bounds__(256)
fc_kernel(const float* __restrict__ emb,
          const float* __restrict__ W,
          const float* __restrict__ b,
          const float* __restrict__ x1,
          float*       __restrict__ out) {
    __shared__ float  es[64][65];
    __shared__ float2 Wp[64][33];   // Wp[k][j] = (W[2j][k], W[2j+1][k])

    int tid = threadIdx.x;

    #pragma unroll
    for (int i = tid; i < 32 * 64; i += 256) {
        int j = i >> 6;
        int k = i & 63;
        Wp[k][j] = make_float2(W[(2 * j) * DD + k], W[(2 * j + 1) * DD + k]);
    }

    int n0 = blockIdx.x * 64;
    #pragma unroll
    for (int i = tid; i < 64 * 16; i += 256) {
        int n  = i >> 4;
        int kq = i & 15;
        float4 v = make_float4(0.f, 0.f, 0.f, 0.f);
        if (n0 + n < NN) v = ((const float4*)emb)[(size_t)(n0 + n) * 16 + kq];
        es[n][4 * kq + 0] = v.x;
        es[n][4 * kq + 1] = v.y;
        es[n][4 * kq + 2] = v.z;
        es[n][4 * kq + 3] = v.w;
    }
    __syncthreads();

    int nl = tid >> 4;
    int cg = tid & 15;
    int c0 = cg * 4;

    float4 bv = *(const float4*)(b + c0);
    unsigned long long bp0 = pk2(bv.x, bv.y);
    unsigned long long bp1 = pk2(bv.z, bv.w);

    unsigned long long acc[4][2];
    #pragma unroll
    for (int i = 0; i < 4; i++) { acc[i][0] = bp0; acc[i][1] = bp1; }

    #pragma unroll 8
    for (int k = 0; k < DD; k++) {
        float2 w0 = Wp[k][2 * cg];
        float2 w1 = Wp[k][2 * cg + 1];
        unsigned long long wp0 = pk2(w0.x, w0.y);
        unsigned long long wp1 = pk2(w1.x, w1.y);
        #pragma unroll
        for (int i = 0; i < 4; i++) {
            float a = es[nl + 16 * i][k];
            unsigned long long ad = pk2(a, a);
            ffma2(acc[i][0], ad, wp0);
            ffma2(acc[i][1], ad, wp1);
        }
    }

    #pragma unroll
    for (int i = 0; i < 4; i++) {
        int n = n0 + nl + 16 * i;
        if (n < NN) {
            size_t idx = (size_t)n * 16 + cg;
            float4 xv = ((const float4*)x1)[idx];
            float l0, h0, l1, h1;
            upk2(l0, h0, acc[i][0]);
            upk2(l1, h1, acc[i][1]);
            float4 o;
            o.x = (l0 + xv.x) * (1.0f / 3.0f);
            o.y = (h0 + xv.y) * (1.0f / 3.0f);
            o.z = (l1 + xv.z) * (1.0f / 3.0f);
            o.w = (h1 + xv.w) * (1.0f / 3.0f);
            ((float4*)out)[idx] = o;
        }
    }
}

extern "C" void kernel_launch(void* const* d_in, const int* in_sizes, int n_in,
                              void* d_out, int out_size) {
    const float* emb  = (const float*)d_in[0];
    const float* W    = (const float*)d_in[1];
    const float* b    = (const float*)d_in[2];
    const float* vals = (const float*)d_in[3];
    const float* du   = (const float*)d_in[4];   // [2, E]
    const int*   rows = (const int*)d_in[5];
    const int*   cols = (const int*)d_in[6];
    float* out = (float*)d_out;

    float*    x1   = nullptr;
    float4*   kept = nullptr;
    unsigned* cnt  = nullptr;
    cudaGetSymbolAddress((void**)&x1,   g_x1);
    cudaGetSymbolAddress((void**)&kept, g_kept);
    cudaGetSymbolAddress((void**)&cnt,  g_cnt);

    // 1) x1 = 0, counters = 0
    int n4 = NN * DD / 4;
    zero_kernel<<<(n4 + 255) / 256, 256>>>(x1, n4);

    // 2) compact kept edges for both layers (v pre-scaled, layer1 has /3)
    prep_kernel<<<(NE + 255) / 256, 256>>>(vals, du, rows, cols);

    // 3) x1 += A1 @ emb
    int sblocks = ((NE + 1) / 2 * 8 + 255) / 256;
    spmm_compact<<<sblocks, 256>>>(emb, kept, cnt, x1);

    // 4) out = (fc(emb) + x1) / 3
    fc_kernel<<<(NN + 63) / 64, 256>>>(emb, W, b, x1, out);

    // 5) out += (A2 @ x1) / 3  (scale folded into kept v)
    spmm_compact<<<sblocks, 256>>>(x1, kept + NE, cnt + 1, out);
}

// round 11
// speedup vs baseline: 1.1389x; 1.1389x over previous
#include <cuda_runtime.h>

#define NN 100000
#define DD 64
#define NE 1200000
#define SCAN_B 1024
#define NBLK ((NN + SCAN_B - 1) / SCAN_B)   // 98

// scratch (__device__ globals per allocation rules)
__device__ float  g_x1[NN * DD];     // 25.6 MB
__device__ int    g_cnt[NN];         // per-row degree
__device__ int    g_ptr[NN];         // exclusive row start
__device__ int    g_cur[NN];         // scatter cursor
__device__ int    g_bsum[NBLK];      // scan block sums
__device__ float4 g_ecsr[NE];        // {col(asfloat), w=vals/0.7, u0, u1}

// ---------------- packed f32x2 helpers ----------------
__device__ __forceinline__ unsigned long long pk2(float lo, float hi) {
    unsigned long long r;
    asm("mov.b64 %0, {%1, %2};" : "=l"(r) : "f"(lo), "f"(hi));
    return r;
}
__device__ __forceinline__ void upk2(float& lo, float& hi, unsigned long long v) {
    asm("mov.b64 {%0, %1}, %2;" : "=f"(lo), "=f"(hi) : "l"(v));
}
__device__ __forceinline__ void ffma2(unsigned long long& d,
                                      unsigned long long a,
                                      unsigned long long b) {
    asm("fma.rn.f32x2 %0, %1, %2, %0;" : "+l"(d) : "l"(a), "l"(b));
}

// ---------------- CSR build ----------------
__global__ void zero_cnt(void) {
    int i = blockIdx.x * blockDim.x + threadIdx.x;
    if (i < NN) g_cnt[i] = 0;
}

__global__ void hist_kernel(const int* __restrict__ rows) {
    int e = blockIdx.x * blockDim.x + threadIdx.x;
    if (e < NE) atomicAdd(&g_cnt[rows[e]], 1);
}

__global__ void scan_block(void) {
    __shared__ int s[SCAN_B];
    int tid = threadIdx.x;
    int i = blockIdx.x * SCAN_B + tid;
    int v = (i < NN) ? g_cnt[i] : 0;
    s[tid] = v;
    __syncthreads();
    #pragma unroll
    for (int off = 1; off < SCAN_B; off <<= 1) {
        int t = (tid >= off) ? s[tid - off] : 0;
        __syncthreads();
        s[tid] += t;
        __syncthreads();
    }
    if (i < NN) g_ptr[i] = s[tid] - v;          // exclusive within block
    if (tid == SCAN_B - 1) g_bsum[blockIdx.x] = s[tid];
}

__global__ void scan_tops(void) {
    if (threadIdx.x == 0) {
        int run = 0;
        for (int b = 0; b < NBLK; b++) {
            int t = g_bsum[b];
            g_bsum[b] = run;
            run += t;
        }
    }
}

__global__ void scan_add(void) {
    int i = blockIdx.x * blockDim.x + threadIdx.x;
    if (i < NN) {
        int p = g_ptr[i] + g_bsum[i / SCAN_B];
        g_ptr[i] = p;
        g_cur[i] = p;
    }
}

__global__ void scatter_kernel(const float* __restrict__ vals,
                               const float* __restrict__ du,
                               const int*   __restrict__ rows,
                               const int*   __restrict__ cols) {
    int e = blockIdx.x * blockDim.x + threadIdx.x;
    if (e >= NE) return;
    int r = rows[e];
    int pos = atomicAdd(&g_cur[r], 1);
    g_ecsr[pos] = make_float4(__int_as_float(cols[e]), vals[e] / 0.7f,
                              du[e], du[e + NE]);
}

// ---------------- CSR SpMM (no atomics) ----------------
// 16 lanes per row, one float4 per lane. Edge loop unrolled x4 for MLP.
// ulane: 0 -> use u0 (layer0), 1 -> use u1 (layer1)
// accumulate: 0 -> out[r] = acc*oscale ; 1 -> out[r] += acc*oscale
__global__ void __launch_bounds__(256)
spmm_csr(const float* __restrict__ x,
         float* __restrict__ out,
         int ulane, float oscale, int accumulate) {
    int tid  = threadIdx.x;
    int lane = tid & 15;
    int r    = blockIdx.x * 16 + (tid >> 4);
    if (r >= NN) return;

    int start = g_ptr[r];
    int deg   = g_cnt[r];

    float4 acc = make_float4(0.f, 0.f, 0.f, 0.f);
    const float4* E = g_ecsr + start;

    int i = 0;
    for (; i + 4 <= deg; i += 4) {
        float4 m0 = E[i + 0];
        float4 m1 = E[i + 1];
        float4 m2 = E[i + 2];
        float4 m3 = E[i + 3];
        float u0 = ulane ? m0.w : m0.z;
        float u1 = ulane ? m1.w : m1.z;
        float u2 = ulane ? m2.w : m2.z;
        float u3 = ulane ? m3.w : m3.z;
        bool k0 = (u0 + 0.7f) >= 1.0f;
        bool k1 = (u1 + 0.7f) >= 1.0f;
        bool k2 = (u2 + 0.7f) >= 1.0f;
        bool k3 = (u3 + 0.7f) >= 1.0f;
        float4 g0, g1, g2, g3;
        if (k0) g0 = ((const float4*)(x + (size_t)__float_as_int(m0.x) * DD))[lane];
        if (k1) g1 = ((const float4*)(x + (size_t)__float_as_int(m1.x) * DD))[lane];
        if (k2) g2 = ((const float4*)(x + (size_t)__float_as_int(m2.x) * DD))[lane];
        if (k3) g3 = ((const float4*)(x + (size_t)__float_as_int(m3.x) * DD))[lane];
        if (k0) { acc.x += m0.y * g0.x; acc.y += m0.y * g0.y;
                  acc.z += m0.y * g0.z; acc.w += m0.y * g0.w; }
        if (k1) { acc.x += m1.y * g1.x; acc.y += m1.y * g1.y;
                  acc.z += m1.y * g1.z; acc.w += m1.y * g1.w; }
        if (k2) { acc.x += m2.y * g2.x; acc.y += m2.y * g2.y;
                  acc.z += m2.y * g2.z; acc.w += m2.y * g2.w; }
        if (k3) { acc.x += m3.y * g3.x; acc.y += m3.y * g3.y;
                  acc.z += m3.y * g3.z; acc.w += m3.y * g3.w; }
    }
    for (; i < deg; i++) {
        float4 m = E[i];
        float u = ulane ? m.w : m.z;
        if ((u + 0.7f) >= 1.0f) {
            float4 g = ((const float4*)(x + (size_t)__float_as_int(m.x) * DD))[lane];
            acc.x += m.y * g.x; acc.y += m.y * g.y;
            acc.z += m.y * g.z; acc.w += m.y * g.w;
        }
    }

    size_t idx = (size_t)r * 16 + lane;
    float4 o;
    if (accumulate) {
        float4 p = ((const float4*)out)[idx];
        o.x = p.x + acc.x * oscale; o.y = p.y + acc.y * oscale;
        o.z = p.z + acc.z * oscale; o.w = p.w + acc.w * oscale;
    } else {
        o.x = acc.x * oscale; o.y = acc.y * oscale;
        o.z = acc.z * oscale; o.w = acc.w * oscale;
    }
    ((float4*)out)[idx] = o;
}

// ---------------- fc (identical to R6 127us version) ----------------
__global__ void __launch_bounds__(256)
fc_kernel(const float* __restrict__ emb,
          const float* __restrict__ W,
          const float* __restrict__ b,
          const float* __restrict__ x1,
          float*       __restrict__ out) {
    __shared__ float  es[64][65];
    __shared__ float2 Wp[64][33];   // Wp[k][j] = (W[2j][k], W[2j+1][k])

    int tid = threadIdx.x;

    #pragma unroll
    for (int i = tid; i < 32 * 64; i += 256) {
        int j = i >> 6;
        int k = i & 63;
        Wp[k][j] = make_float2(W[(2 * j) * DD + k], W[(2 * j + 1) * DD + k]);
    }

    int n0 = blockIdx.x * 64;
    #pragma unroll
    for (int i = tid; i < 64 * 16; i += 256) {
        int n  = i >> 4;
        int kq = i & 15;
        float4 v = make_float4(0.f, 0.f, 0.f, 0.f);
        if (n0 + n < NN) v = ((const float4*)emb)[(size_t)(n0 + n) * 16 + kq];
        es[n][4 * kq + 0] = v.x;
        es[n][4 * kq + 1] = v.y;
        es[n][4 * kq + 2] = v.z;
        es[n][4 * kq + 3] = v.w;
    }
    __syncthreads();

    int nl = tid >> 4;
    int cg = tid & 15;
    int c0 = cg * 4;

    float4 bv = *(const float4*)(b + c0);
    unsigned long long bp0 = pk2(bv.x, bv.y);
    unsigned long long bp1 = pk2(bv.z, bv.w);

    unsigned long long acc[4][2];
    #pragma unroll
    for (int i = 0; i < 4; i++) { acc[i][0] = bp0; acc[i][1] = bp1; }

    #pragma unroll 8
    for (int k = 0; k < DD; k++) {
        float2 w0 = Wp[k][2 * cg];
        float2 w1 = Wp[k][2 * cg + 1];
        unsigned long long wp0 = pk2(w0.x, w0.y);
        unsigned long long wp1 = pk2(w1.x, w1.y);
        #pragma unroll
        for (int i = 0; i < 4; i++) {
            float a = es[nl + 16 * i][k];
            unsigned long long ad = pk2(a, a);
            ffma2(acc[i][0], ad, wp0);
            ffma2(acc[i][1], ad, wp1);
        }
    }

    #pragma unroll
    for (int i = 0; i < 4; i++) {
        int n = n0 + nl + 16 * i;
        if (n < NN) {
            size_t idx = (size_t)n * 16 + cg;
            float4 xv = ((const float4*)x1)[idx];
            float l0, h0, l1, h1;
            upk2(l0, h0, acc[i][0]);
            upk2(l1, h1, acc[i][1]);
            float4 o;
            o.x = (l0 + xv.x) * (1.0f / 3.0f);
            o.y = (h0 + xv.y) * (1.0f / 3.0f);
            o.z = (l1 + xv.z) * (1.0f / 3.0f);
            o.w = (h1 + xv.w) * (1.0f / 3.0f);
            ((float4*)out)[idx] = o;
        }
    }
}

extern "C" void kernel_launch(void* const* d_in, const int* in_sizes, int n_in,
                              void* d_out, int out_size) {
    const float* emb  = (const float*)d_in[0];
    const float* W    = (const float*)d_in[1];
    const float* b    = (const float*)d_in[2];
    const float* vals = (const float*)d_in[3];
    const float* du   = (const float*)d_in[4];   // [2, E]
    const int*   rows = (const int*)d_in[5];
    const int*   cols = (const int*)d_in[6];
    float* out = (float*)d_out;

    float* x1 = nullptr;
    cudaGetSymbolAddress((void**)&x1, g_x1);

    // ---- CSR build (int atomics only) ----
    zero_cnt<<<(NN + 255) / 256, 256>>>();
    hist_kernel<<<(NE + 255) / 256, 256>>>(rows);
    scan_block<<<NBLK, SCAN_B>>>();
    scan_tops<<<1, 32>>>();
    scan_add<<<(NN + 255) / 256, 256>>>();
    scatter_kernel<<<(NE + 255) / 256, 256>>>(vals, du, rows, cols);

    // ---- layer 0: x1 = A1 @ emb  (writes every row; no zero pass needed) ----
    int sgrid = (NN + 15) / 16;
    spmm_csr<<<sgrid, 256>>>(emb, x1, 0, 1.0f, 0);

    // ---- fc: out = (emb@W^T + b + x1) / 3 ----
    fc_kernel<<<(NN + 63) / 64, 256>>>(emb, W, b, x1, out);

    // ---- layer 1: out += (A2 @ x1) / 3  (non-atomic RMW, row-owned) ----
    spmm_csr<<<sgrid, 256>>>(x1, out, 1, 1.0f / 3.0f, 1);
}

// round 12
// speedup vs baseline: 1.5448x; 1.3564x over previous
#include <cuda_runtime.h>

#define NN 100000
#define DD 64
#define NE 1200000
#define NEH (NE / 2)

// scratch: x1 = A1 @ all_emb  (25.6 MB, __device__ global per allocation rules)
__device__ float g_x1[NN * DD];

// ---------------- packed f32x2 helpers ----------------
__device__ __forceinline__ unsigned long long pk2(float lo, float hi) {
    unsigned long long r;
    asm("mov.b64 %0, {%1, %2};" : "=l"(r) : "f"(lo), "f"(hi));
    return r;
}
__device__ __forceinline__ void upk2(float& lo, float& hi, unsigned long long v) {
    asm("mov.b64 {%0, %1}, %2;" : "=f"(lo), "=f"(hi) : "l"(v));
}
__device__ __forceinline__ void ffma2(unsigned long long& d,
                                      unsigned long long a,
                                      unsigned long long b) {
    asm("fma.rn.f32x2 %0, %1, %2, %0;" : "+l"(d) : "l"(a), "l"(b));
}

__device__ __forceinline__ void red_add_v4(float* addr, float a, float b,
                                           float c, float d) {
    asm volatile("red.global.add.v4.f32 [%0], {%1, %2, %3, %4};"
                 :: "l"(addr), "f"(a), "f"(b), "f"(c), "f"(d)
                 : "memory");
}

__global__ void zero_kernel(float* __restrict__ p, int n4) {
    int i = blockIdx.x * blockDim.x + threadIdx.x;
    if (i < n4) ((float4*)p)[i] = make_float4(0.f, 0.f, 0.f, 0.f);
}

// R6-proven spmm: TWO edges per thread (e, e+NE/2), 8 lanes/edge, 2 float4
// per lane; unconditional parallel metadata loads; predicated gather+red.
__global__ void spmm_kernel(const float* __restrict__ x,
                            const float* __restrict__ vals,
                            const float* __restrict__ du,
                            const int*   __restrict__ rows,
                            const int*   __restrict__ cols,
                            float*       __restrict__ out,
                            float scale) {
    unsigned gid = blockIdx.x * blockDim.x + threadIdx.x;
    unsigned e0  = gid >> 3;
    if (e0 >= NEH) return;
    unsigned e1   = e0 + NEH;
    unsigned lane = gid & 7u;

    float u0 = du[e0],  u1 = du[e1];
    float w0 = vals[e0], w1 = vals[e1];
    int   c0 = cols[e0], c1 = cols[e1];
    int   r0 = rows[e0], r1 = rows[e1];

    bool k0 = (u0 + 0.7f) >= 1.0f;   // matches reference f32 exactly
    bool k1 = (u1 + 0.7f) >= 1.0f;
    float v0 = (w0 / 0.7f) * scale;
    float v1 = (w1 / 0.7f) * scale;

    float4 a0, a1, b0, b1;
    const float4* s0 = (const float4*)(x + (size_t)c0 * DD);
    const float4* s1 = (const float4*)(x + (size_t)c1 * DD);
    if (k0) { a0 = s0[lane]; a1 = s0[lane + 8]; }
    if (k1) { b0 = s1[lane]; b1 = s1[lane + 8]; }

    if (k0) {
        float* d0 = out + (size_t)r0 * DD;
        red_add_v4(d0 + lane * 4,       v0 * a0.x, v0 * a0.y, v0 * a0.z, v0 * a0.w);
        red_add_v4(d0 + (lane + 8) * 4, v0 * a1.x, v0 * a1.y, v0 * a1.z, v0 * a1.w);
    }
    if (k1) {
        float* d1 = out + (size_t)r1 * DD;
        red_add_v4(d1 + lane * 4,       v1 * b0.x, v1 * b0.y, v1 * b0.z, v1 * b0.w);
        red_add_v4(d1 + (lane + 8) * 4, v1 * b1.x, v1 * b1.y, v1 * b1.z, v1 * b1.w);
    }
}

// fc v2: out[n][c] = (dot(emb[n], W[c]) + b[c] + x1[n][c]) / 3.
// Tile: 64 nodes x 64 cols, 128 threads. Thread = 4 node-PAIRS x 4 cols
// = 16 f32x2 accumulators paired over adjacent nodes.
//   est[k][n] transposed emb tile -> a-operand is a direct LDS.64 (no movs)
//   Wt[k][c]  transposed W        -> one LDS.128 per k (4 cols), 4 dup-packs
//                                    hoisted across the 4 node pairs.
__global__ void __launch_bounds__(128)
fc_kernel(const float* __restrict__ emb,
          const float* __restrict__ W,
          const float* __restrict__ b,
          const float* __restrict__ x1,
          float*       __restrict__ out) {
    __shared__ float est[DD][66];   // [k][node], pad 2 (even stride: LDS.64 ok)
    __shared__ float Wt[DD][68];    // [k][col], stride mult of 4: LDS.128 ok

    int tid = threadIdx.x;          // 0..127
    int ng  = tid >> 4;             // node-pair group 0..7
    int cg  = tid & 15;             // col group: cols 4*cg..4*cg+3

    // stage W transposed: Wt[k][c] = W[c*64 + k]
    #pragma unroll
    for (int i = tid; i < DD * DD; i += 128) {
        int c = i >> 6;
        int k = i & 63;
        Wt[k][c] = W[c * DD + k];
    }

    // stage emb tile transposed: est[k][n] (coalesced float4 global reads)
    int n0 = blockIdx.x * 64;
    #pragma unroll
    for (int i = tid; i < 64 * 16; i += 128) {
        int n  = i >> 4;
        int kq = i & 15;
        float4 v = make_float4(0.f, 0.f, 0.f, 0.f);
        if (n0 + n < NN) v = ((const float4*)emb)[(size_t)(n0 + n) * 16 + kq];
        est[4 * kq + 0][n] = v.x;
        est[4 * kq + 1][n] = v.y;
        est[4 * kq + 2][n] = v.z;
        est[4 * kq + 3][n] = v.w;
    }
    __syncthreads();

    // bias init: acc[i][c] is (node_even, node_odd) for col 4*cg+c -> dup b
    unsigned long long acc[4][4];
    {
        float4 bv = *(const float4*)(b + 4 * cg);
        unsigned long long b0 = pk2(bv.x, bv.x);
        unsigned long long b1 = pk2(bv.y, bv.y);
        unsigned long long b2 = pk2(bv.z, bv.z);
        unsigned long long b3 = pk2(bv.w, bv.w);
        #pragma unroll
        for (int i = 0; i < 4; i++) {
            acc[i][0] = b0; acc[i][1] = b1; acc[i][2] = b2; acc[i][3] = b3;
        }
    }

    #pragma unroll 8
    for (int k = 0; k < DD; k++) {
        // a: 4 node-pairs, direct 8B shared loads into f32x2 pairs
        unsigned long long ap[4];
        #pragma unroll
        for (int i = 0; i < 4; i++)
            ap[i] = *(const unsigned long long*)&est[k][2 * (ng + 8 * i)];
        // w: 4 cols in one LDS.128, dup-packed once, reused over 4 pairs
        float4 wv = *(const float4*)&Wt[k][4 * cg];
        unsigned long long wd0 = pk2(wv.x, wv.x);
        unsigned long long wd1 = pk2(wv.y, wv.y);
        unsigned long long wd2 = pk2(wv.z, wv.z);
        unsigned long long wd3 = pk2(wv.w, wv.w);
        #pragma unroll
        for (int i = 0; i < 4; i++) {
            ffma2(acc[i][0], ap[i], wd0);
            ffma2(acc[i][1], ap[i], wd1);
            ffma2(acc[i][2], ap[i], wd2);
            ffma2(acc[i][3], ap[i], wd3);
        }
    }

    // epilogue: per node pair -> two float4 rows, fuse +x1 and *1/3
    #pragma unroll
    for (int i = 0; i < 4; i++) {
        float lo0, hi0, lo1, hi1, lo2, hi2, lo3, hi3;
        upk2(lo0, hi0, acc[i][0]);
        upk2(lo1, hi1, acc[i][1]);
        upk2(lo2, hi2, acc[i][2]);
        upk2(lo3, hi3, acc[i][3]);
        int nbase = n0 + 2 * (ng + 8 * i);
        if (nbase < NN) {
            size_t idx = (size_t)nbase * 16 + cg;
            float4 xv = ((const float4*)x1)[idx];
            float4 o;
            o.x = (lo0 + xv.x) * (1.0f / 3.0f);
            o.y = (lo1 + xv.y) * (1.0f / 3.0f);
            o.z = (lo2 + xv.z) * (1.0f / 3.0f);
            o.w = (lo3 + xv.w) * (1.0f / 3.0f);
            ((float4*)out)[idx] = o;
        }
        if (nbase + 1 < NN) {
            size_t idx = (size_t)(nbase + 1) * 16 + cg;
            float4 xv = ((const float4*)x1)[idx];
            float4 o;
            o.x = (hi0 + xv.x) * (1.0f / 3.0f);
            o.y = (hi1 + xv.y) * (1.0f / 3.0f);
            o.z = (hi2 + xv.z) * (1.0f / 3.0f);
            o.w = (hi3 + xv.w) * (1.0f / 3.0f);
            ((float4*)out)[idx] = o;
        }
    }
}

extern "C" void kernel_launch(void* const* d_in, const int* in_sizes, int n_in,
                              void* d_out, int out_size) {
    const float* emb  = (const float*)d_in[0];
    const float* W    = (const float*)d_in[1];
    const float* b    = (const float*)d_in[2];
    const float* vals = (const float*)d_in[3];
    const float* du   = (const float*)d_in[4];   // [2, E]
    const int*   rows = (const int*)d_in[5];
    const int*   cols = (const int*)d_in[6];
    float* out = (float*)d_out;

    float* x1 = nullptr;
    cudaGetSymbolAddress((void**)&x1, g_x1);

    // 1) x1 = 0
    int n4 = NN * DD / 4;
    zero_kernel<<<(n4 + 255) / 256, 256>>>(x1, n4);

    // 2) x1 += A1 @ emb   (layer-0 dropout)
    int sblocks = (NEH * 8 + 255) / 256;
    spmm_kernel<<<sblocks, 256>>>(emb, vals, du, rows, cols, x1, 1.0f);

    // 3) out = (fc(emb) + x1) / 3   (node-paired FFMA2 register tile)
    fc_kernel<<<(NN + 63) / 64, 128>>>(emb, W, b, x1, out);

    // 4) out += (A2 @ x1) / 3   (layer-1 dropout, /3 folded into edge weight)
    spmm_kernel<<<sblocks, 256>>>(x1, vals, du + NE, rows, cols, out,
                                  1.0f / 3.0f);
}